// round 1
// baseline (speedup 1.0000x reference)
#include <cuda_runtime.h>

// MeanAggregator: out = concat([x, mean(neg, axis=1)]) @ w   for src and dst
// N=50000 rows each, S=25 neighbors, D=128, OUT=128, K=2D=256.
// Fused single pass: stage A builds cat-tile [32 x 256] in smem (streams the
// 1.28 GB of neighbor data exactly once), stage B does a register-blocked
// 32x128 fp32 GEMM against w (L1/L2-resident).

#define N_NODES 50000
#define S_NEIGH 25
#define DIM     128
#define OUTD    128
#define KDIM    256        // 2*DIM
#define TM      32         // row-tasks per block
#define THREADS 256
#define A_STRIDE (KDIM + 4)   // 260 floats; multiple of 4 -> rows stay 16B-aligned

__global__ __launch_bounds__(THREADS, 3)
void magg_kernel(const float* __restrict__ src,
                 const float* __restrict__ src_neg,
                 const float* __restrict__ dst,
                 const float* __restrict__ dst_neg,
                 const float* __restrict__ w,
                 float* __restrict__ out)
{
    __shared__ float A[TM][A_STRIDE];   // [row][k] cat tile, 33.3 KB

    const int tid = threadIdx.x;
    const long t0 = (long)blockIdx.x * TM;   // first task of this block

    // ---------------- Stage A: build cat tile ----------------
    // 32 rows * 32 float4-chunks = 1024 work items; 4 per thread.
    // Each item: 1 float4 of x + 25 float4 of neg (mean).
    for (int i = tid; i < TM * (DIM / 4); i += THREADS) {
        const int r  = i >> 5;            // row within tile (0..31)
        const int d4 = (i & 31) << 2;     // feature offset (0,4,...,124)
        const long task = t0 + r;

        const float* xptr;
        const float* nptr;
        long row;
        if (task < N_NODES) { xptr = src; nptr = src_neg; row = task; }
        else                { xptr = dst; nptr = dst_neg; row = task - N_NODES; }

        const float4 xv = *reinterpret_cast<const float4*>(xptr + row * DIM + d4);

        const float* np = nptr + row * (long)(S_NEIGH * DIM) + d4;
        float4 s = make_float4(0.f, 0.f, 0.f, 0.f);
        #pragma unroll
        for (int j = 0; j < S_NEIGH; j++) {
            const float4 v = *reinterpret_cast<const float4*>(np + j * DIM);
            s.x += v.x; s.y += v.y; s.z += v.z; s.w += v.w;
        }
        const float inv = 1.0f / (float)S_NEIGH;

        *reinterpret_cast<float4*>(&A[r][d4])       = xv;
        float4 m = make_float4(s.x * inv, s.y * inv, s.z * inv, s.w * inv);
        *reinterpret_cast<float4*>(&A[r][DIM + d4]) = m;
    }
    __syncthreads();

    // ---------------- Stage B: 32x128 GEMM, K=256 ----------------
    // Thread grid: tx = tid&31 -> 4 consecutive output cols (tx*4 .. tx*4+3)
    //              ty = tid>>5 -> 4 consecutive rows (ty*4 .. ty*4+3)
    // Per k: 1 coalesced LDG.128 of w row, broadcast LDS.128 of A, 16 FMA.
    const int tx = tid & 31;
    const int ty = tid >> 5;
    const int r0 = ty << 2;          // first row of this thread's micro-tile
    const int c0 = tx << 2;          // first col

    float4 acc0 = make_float4(0.f,0.f,0.f,0.f);
    float4 acc1 = make_float4(0.f,0.f,0.f,0.f);
    float4 acc2 = make_float4(0.f,0.f,0.f,0.f);
    float4 acc3 = make_float4(0.f,0.f,0.f,0.f);

    #pragma unroll 4
    for (int k4 = 0; k4 < KDIM / 4; k4++) {
        // 4 rows of A, 4 k-values each (broadcast within warp, conflict-free)
        const float4 a0 = *reinterpret_cast<const float4*>(&A[r0 + 0][k4 << 2]);
        const float4 a1 = *reinterpret_cast<const float4*>(&A[r0 + 1][k4 << 2]);
        const float4 a2 = *reinterpret_cast<const float4*>(&A[r0 + 2][k4 << 2]);
        const float4 a3 = *reinterpret_cast<const float4*>(&A[r0 + 3][k4 << 2]);

        const float* ak0 = reinterpret_cast<const float*>(&a0);
        const float* ak1 = reinterpret_cast<const float*>(&a1);
        const float* ak2 = reinterpret_cast<const float*>(&a2);
        const float* ak3 = reinterpret_cast<const float*>(&a3);

        #pragma unroll
        for (int kk = 0; kk < 4; kk++) {
            const int k = (k4 << 2) + kk;
            const float4 wv = *reinterpret_cast<const float4*>(w + (long)k * OUTD + c0);

            const float b0 = ak0[kk], b1 = ak1[kk], b2 = ak2[kk], b3 = ak3[kk];

            acc0.x += b0 * wv.x; acc0.y += b0 * wv.y; acc0.z += b0 * wv.z; acc0.w += b0 * wv.w;
            acc1.x += b1 * wv.x; acc1.y += b1 * wv.y; acc1.z += b1 * wv.z; acc1.w += b1 * wv.w;
            acc2.x += b2 * wv.x; acc2.y += b2 * wv.y; acc2.z += b2 * wv.z; acc2.w += b2 * wv.w;
            acc3.x += b3 * wv.x; acc3.y += b3 * wv.y; acc3.z += b3 * wv.z; acc3.w += b3 * wv.w;
        }
    }

    // ---------------- Write out ----------------
    // out layout: re_src rows [0,N), re_dst rows [N,2N) -> offset = task*OUTD.
    {
        const long task = t0 + r0;
        float* o = out + task * (long)OUTD + c0;
        *reinterpret_cast<float4*>(o)            = acc0;
        *reinterpret_cast<float4*>(o + OUTD)     = acc1;
        *reinterpret_cast<float4*>(o + 2 * OUTD) = acc2;
        *reinterpret_cast<float4*>(o + 3 * OUTD) = acc3;
    }
}

extern "C" void kernel_launch(void* const* d_in, const int* in_sizes, int n_in,
                              void* d_out, int out_size)
{
    const float* src     = (const float*)d_in[0];
    const float* src_neg = (const float*)d_in[1];
    const float* dst     = (const float*)d_in[2];
    const float* dst_neg = (const float*)d_in[3];
    const float* w       = (const float*)d_in[4];
    float* out = (float*)d_out;

    const int n_tasks = 2 * N_NODES;                  // 100000
    dim3 grid((n_tasks + TM - 1) / TM);               // 3125 blocks
    magg_kernel<<<grid, THREADS>>>(src, src_neg, dst, dst_neg, w, out);
}

// round 2
// speedup vs baseline: 1.0348x; 1.0348x over previous
#include <cuda_runtime.h>

// Fused MeanAggregator, round 2: persistent blocks, double-buffered cat tile,
// neighbor streaming for tile t+1 software-pipelined INSIDE the GEMM of tile t.
// Goal: overlap the ~175us HBM stream with the ~178us fp32 FMA work.

#define N_NODES 50000
#define S_NEIGH 25
#define DIM     128
#define OUTD    128
#define KDIM    256
#define TM      32
#define THREADS 256
#define A_STRIDE (KDIM + 4)          // 260 floats, rows 16B-aligned
#define NT      (2 * N_NODES / TM)   // 3125 tiles
#define GRID    296                  // 2 blocks per SM, one wave

__device__ __forceinline__ float4 ld4(const float* p) {
    return *reinterpret_cast<const float4*>(p);
}
__device__ __forceinline__ void add4(float4& a, const float4 b) {
    a.x += b.x; a.y += b.y; a.z += b.z; a.w += b.w;
}

__global__ __launch_bounds__(THREADS, 2)
void magg_kernel(const float* __restrict__ src,
                 const float* __restrict__ src_neg,
                 const float* __restrict__ dst,
                 const float* __restrict__ dst_neg,
                 const float* __restrict__ w,
                 float* __restrict__ out)
{
    __shared__ float A[2][TM][A_STRIDE];   // 66.6 KB (double buffer)

    const int tid = threadIdx.x;
    const int tx  = tid & 31;
    const int ty  = tid >> 5;
    const int d4  = tx << 2;   // aggregation feature chunk (same for all 4 items)
    const int c0  = tx << 2;   // GEMM first output col
    const int r0  = ty << 2;   // GEMM first row of 4x4 micro-tile

    int cur = blockIdx.x;
    int buf = 0;

    // ---------------- prologue: blocking aggregation of first tile ----------------
    {
        const long t0 = (long)cur * TM;
        #pragma unroll
        for (int it = 0; it < 4; it++) {
            const int  r    = ty + (it << 3);
            const long task = t0 + r;
            const float* xp; const float* np;
            if (task < N_NODES) { xp = src + task * DIM; np = src_neg + task * (long)(S_NEIGH * DIM); }
            else { const long rr = task - N_NODES; xp = dst + rr * DIM; np = dst_neg + rr * (long)(S_NEIGH * DIM); }
            float4 sum = make_float4(0.f, 0.f, 0.f, 0.f);
            #pragma unroll
            for (int j = 0; j < S_NEIGH; j++) add4(sum, ld4(np + j * DIM + d4));
            const float inv = 1.0f / (float)S_NEIGH;
            *reinterpret_cast<float4*>(&A[0][r][d4]) = ld4(xp + d4);
            float4 m = make_float4(sum.x * inv, sum.y * inv, sum.z * inv, sum.w * inv);
            *reinterpret_cast<float4*>(&A[0][r][DIM + d4]) = m;
        }
    }
    __syncthreads();

    // ---------------- persistent loop: GEMM(tile) fused with agg(tile+GRID) ----------------
    while (true) {
        const int  nxt = cur + GRID;
        const bool hn  = nxt < NT;

        const float* nb_ptr[4];
        const float* xb_ptr[4];
        if (hn) {
            const long t0n = (long)nxt * TM;
            #pragma unroll
            for (int it = 0; it < 4; it++) {
                const long task = t0n + ty + (it << 3);
                if (task < N_NODES) {
                    nb_ptr[it] = src_neg + task * (long)(S_NEIGH * DIM) + d4;
                    xb_ptr[it] = src + task * DIM + d4;
                } else {
                    const long rr = task - N_NODES;
                    nb_ptr[it] = dst_neg + rr * (long)(S_NEIGH * DIM) + d4;
                    xb_ptr[it] = dst + rr * DIM + d4;
                }
            }
        }

        float4 s0 = make_float4(0.f,0.f,0.f,0.f), s1 = s0, s2 = s0, s3 = s0;
        float4 nb[2][2];
        float4 xv0, xv1, xv2, xv3;
        float4 acc0 = make_float4(0.f,0.f,0.f,0.f), acc1 = acc0, acc2 = acc0, acc3 = acc0;

        const float* Ab = &A[buf][0][0];

        #pragma unroll 4
        for (int t = 0; t < 64; t++) {
            // ---- consume the neighbor pair issued 2 chunks ago (slack ~2 GEMM chunks) ----
            if (hn && t >= 2 && t < 54) {
                const int pt   = t - 2;
                const int item = pt & 3;            // static under unroll-4
                const int j    = (pt >> 2) << 1;
                float4* sp = (item == 0) ? &s0 : (item == 1) ? &s1 : (item == 2) ? &s2 : &s3;
                add4(*sp, nb[pt & 1][0]);
                if (j + 1 < S_NEIGH) add4(*sp, nb[pt & 1][1]);
            }
            // ---- issue streaming loads for the NEXT tile ----
            if (hn) {
                if (t < 52) {
                    const int item = t & 3;          // static under unroll-4
                    const int j    = (t >> 2) << 1;
                    const float* p = ((item == 0) ? nb_ptr[0] : (item == 1) ? nb_ptr[1]
                                     : (item == 2) ? nb_ptr[2] : nb_ptr[3]) + j * DIM;
                    nb[t & 1][0] = ld4(p);
                    if (j + 1 < S_NEIGH) nb[t & 1][1] = ld4(p + DIM);
                } else if (t < 56) {
                    const int item = t & 3;
                    const float4 x = ld4((item == 0) ? xb_ptr[0] : (item == 1) ? xb_ptr[1]
                                        : (item == 2) ? xb_ptr[2] : xb_ptr[3]);
                    if (item == 0) xv0 = x; else if (item == 1) xv1 = x;
                    else if (item == 2) xv2 = x; else xv3 = x;
                }
            }

            // ---- GEMM chunk: k = 4t..4t+3 ----
            const float4 a0 = ld4(Ab + (r0 + 0) * A_STRIDE + (t << 2));
            const float4 a1 = ld4(Ab + (r0 + 1) * A_STRIDE + (t << 2));
            const float4 a2 = ld4(Ab + (r0 + 2) * A_STRIDE + (t << 2));
            const float4 a3 = ld4(Ab + (r0 + 3) * A_STRIDE + (t << 2));
            #pragma unroll
            for (int kk = 0; kk < 4; kk++) {
                const float4 wv = ld4(w + (long)((t << 2) + kk) * OUTD + c0);
                const float b0 = (&a0.x)[kk], b1 = (&a1.x)[kk], b2 = (&a2.x)[kk], b3 = (&a3.x)[kk];
                acc0.x += b0 * wv.x; acc0.y += b0 * wv.y; acc0.z += b0 * wv.z; acc0.w += b0 * wv.w;
                acc1.x += b1 * wv.x; acc1.y += b1 * wv.y; acc1.z += b1 * wv.z; acc1.w += b1 * wv.w;
                acc2.x += b2 * wv.x; acc2.y += b2 * wv.y; acc2.z += b2 * wv.z; acc2.w += b2 * wv.w;
                acc3.x += b3 * wv.x; acc3.y += b3 * wv.y; acc3.z += b3 * wv.z; acc3.w += b3 * wv.w;
            }
        }

        // ---- finish aggregation for next tile -> A[buf^1] ----
        if (hn) {
            const float inv = 1.0f / (float)S_NEIGH;
            float* An = &A[buf ^ 1][0][0];
            #pragma unroll
            for (int it = 0; it < 4; it++) {
                const int r = ty + (it << 3);
                const float4 xi = (it == 0) ? xv0 : (it == 1) ? xv1 : (it == 2) ? xv2 : xv3;
                const float4 si = (it == 0) ? s0  : (it == 1) ? s1  : (it == 2) ? s2  : s3;
                *reinterpret_cast<float4*>(An + r * A_STRIDE + d4) = xi;
                float4 m = make_float4(si.x * inv, si.y * inv, si.z * inv, si.w * inv);
                *reinterpret_cast<float4*>(An + r * A_STRIDE + DIM + d4) = m;
            }
        }

        // ---- write GEMM output for current tile ----
        {
            const long task = (long)cur * TM + r0;
            float* o = out + task * (long)OUTD + c0;
            *reinterpret_cast<float4*>(o)            = acc0;
            *reinterpret_cast<float4*>(o + OUTD)     = acc1;
            *reinterpret_cast<float4*>(o + 2 * OUTD) = acc2;
            *reinterpret_cast<float4*>(o + 3 * OUTD) = acc3;
        }

        __syncthreads();
        if (!hn) break;
        cur = nxt;
        buf ^= 1;
    }
}

extern "C" void kernel_launch(void* const* d_in, const int* in_sizes, int n_in,
                              void* d_out, int out_size)
{
    const float* src     = (const float*)d_in[0];
    const float* src_neg = (const float*)d_in[1];
    const float* dst     = (const float*)d_in[2];
    const float* dst_neg = (const float*)d_in[3];
    const float* w       = (const float*)d_in[4];
    float* out = (float*)d_out;

    magg_kernel<<<GRID, THREADS>>>(src, src_neg, dst, dst_neg, w, out);
}

// round 3
// speedup vs baseline: 1.6803x; 1.6238x over previous
#include <cuda_runtime.h>

// Round 3: warp-specialized producer/consumer MeanAggregator.
//   warps 0-3 (producers): stream neighbors of tile t+1, build cat tile in smem
//   warps 4-7 (consumers): 32x128 fp32 GEMM of tile t against w
// Double-buffered smem tile; one __syncthreads per tile. DRAM stream and FMA
// stream run concurrently on every SM.

#define N_NODES 50000
#define S_NEIGH 25
#define DIM     128
#define OUTD    128
#define KDIM    256
#define TM      32
#define THREADS 256
#define A_STRIDE 260            // floats per tile row (16B-aligned, pad vs 256)
#define NT      3125            // 2*N_NODES / TM
#define GRID    296             // 2 persistent blocks per SM

// ---- packed f32x2 helpers (Blackwell) ----
__device__ __forceinline__ unsigned long long fadd2(unsigned long long a, unsigned long long b) {
    unsigned long long d;
    asm("add.rn.f32x2 %0, %1, %2;" : "=l"(d) : "l"(a), "l"(b));
    return d;
}
__device__ __forceinline__ unsigned long long fmul2(unsigned long long a, unsigned long long b) {
    unsigned long long d;
    asm("mul.rn.f32x2 %0, %1, %2;" : "=l"(d) : "l"(a), "l"(b));
    return d;
}
// 16B streaming load (evict-first: don't pollute L1/L2 with the 1.28GB stream)
__device__ __forceinline__ ulonglong2 ldcs16(const float* p) {
    ulonglong2 v;
    asm volatile("ld.global.cs.v2.u64 {%0, %1}, [%2];"
                 : "=l"(v.x), "=l"(v.y) : "l"(p));
    return v;
}
__device__ __forceinline__ float4 ld4(const float* p) {
    return *reinterpret_cast<const float4*>(p);
}

// Build rows of the cat tile: Adst[r][0:128) = x, Adst[r][128:256) = mean(neg)
__device__ __forceinline__ void produce_tile(
    float* __restrict__ Adst, int tile,
    const float* __restrict__ src, const float* __restrict__ src_neg,
    const float* __restrict__ dst, const float* __restrict__ dst_neg,
    int ptid, int pthreads, unsigned long long inv2)
{
    const long t0 = (long)tile * TM;
    for (int i = ptid; i < TM * (DIM / 4); i += pthreads) {
        const int r  = i >> 5;            // row 0..31
        const int d4 = (i & 31) << 2;     // feature chunk
        const long task = t0 + r;

        const float* xp; const float* np;
        if (task < N_NODES) {
            xp = src + task * DIM;
            np = src_neg + task * (long)(S_NEIGH * DIM);
        } else {
            const long rr = task - N_NODES;
            xp = dst + rr * DIM;
            np = dst_neg + rr * (long)(S_NEIGH * DIM);
        }

        unsigned long long s0 = 0ull, s1 = 0ull;      // {0,0} packed
        const float* p = np + d4;
        #pragma unroll
        for (int j = 0; j < S_NEIGH; j++) {
            const ulonglong2 v = ldcs16(p + j * DIM);
            s0 = fadd2(s0, v.x);
            s1 = fadd2(s1, v.y);
        }
        const ulonglong2 xv = *reinterpret_cast<const ulonglong2*>(xp + d4);

        ulonglong2 m;
        m.x = fmul2(s0, inv2);
        m.y = fmul2(s1, inv2);

        *reinterpret_cast<ulonglong2*>(Adst + r * A_STRIDE + d4)       = xv;
        *reinterpret_cast<ulonglong2*>(Adst + r * A_STRIDE + DIM + d4) = m;
    }
}

__global__ __launch_bounds__(THREADS, 2)
void magg_kernel(const float* __restrict__ src,
                 const float* __restrict__ src_neg,
                 const float* __restrict__ dst,
                 const float* __restrict__ dst_neg,
                 const float* __restrict__ w,
                 float* __restrict__ out)
{
    __shared__ float A[2][TM][A_STRIDE];   // 66.6 KB double buffer

    const int tid  = threadIdx.x;
    const int wid  = tid >> 5;
    const int lane = tid & 31;

    unsigned long long inv2;
    asm("mov.b64 %0, {%1, %1};" : "=l"(inv2) : "f"(1.0f / (float)S_NEIGH));

    // ---- prologue: all 8 warps build the first tile ----
    produce_tile(&A[0][0][0], blockIdx.x, src, src_neg, dst, dst_neg,
                 tid, THREADS, inv2);
    __syncthreads();

    int buf = 0;
    for (int t = blockIdx.x; t < NT; t += GRID) {
        const int nxt = t + GRID;

        if (wid < 4) {
            // ---------------- producers: build tile t+GRID ----------------
            if (nxt < NT) {
                produce_tile(&A[buf ^ 1][0][0], nxt, src, src_neg, dst, dst_neg,
                             tid, 128, inv2);
            }
        } else {
            // ---------------- consumers: GEMM tile t ----------------
            // warp cw handles rows 8cw..8cw+7; lane handles cols 4*lane..+3
            const int cw = wid - 4;
            const int r0 = cw << 3;
            const int c0 = lane << 2;
            const float* Ab = &A[buf][0][0];

            float4 acc[8];
            #pragma unroll
            for (int j = 0; j < 8; j++) acc[j] = make_float4(0.f, 0.f, 0.f, 0.f);

            #pragma unroll 2
            for (int k4 = 0; k4 < KDIM / 4; k4++) {
                float4 a[8];
                #pragma unroll
                for (int j = 0; j < 8; j++)
                    a[j] = ld4(Ab + (r0 + j) * A_STRIDE + (k4 << 2));  // broadcast LDS.128

                #pragma unroll
                for (int kk = 0; kk < 4; kk++) {
                    const float4 wv = ld4(w + (long)((k4 << 2) + kk) * OUTD + c0);
                    #pragma unroll
                    for (int j = 0; j < 8; j++) {
                        const float b = (&a[j].x)[kk];
                        acc[j].x += b * wv.x;
                        acc[j].y += b * wv.y;
                        acc[j].z += b * wv.z;
                        acc[j].w += b * wv.w;
                    }
                }
            }

            const long row0 = (long)t * TM + r0;
            float* o = out + row0 * OUTD + c0;
            #pragma unroll
            for (int j = 0; j < 8; j++)
                *reinterpret_cast<float4*>(o + (long)j * OUTD) = acc[j];
        }

        __syncthreads();
        buf ^= 1;
    }
}

extern "C" void kernel_launch(void* const* d_in, const int* in_sizes, int n_in,
                              void* d_out, int out_size)
{
    const float* src     = (const float*)d_in[0];
    const float* src_neg = (const float*)d_in[1];
    const float* dst     = (const float*)d_in[2];
    const float* dst_neg = (const float*)d_in[3];
    const float* w       = (const float*)d_in[4];
    float* out = (float*)d_out;

    magg_kernel<<<GRID, THREADS>>>(src, src_neg, dst, dst_neg, w, out);
}